// round 14
// baseline (speedup 1.0000x reference)
#include <cuda_runtime.h>
#include <cuda_bf16.h>
#include <cstdint>

#define Bq 256      // queries
#define Dk 768      // feature dim
#define Nn 131072   // database rows
#define Lo 512      // output row length

#define MARGIN 0.2f
#define NT8 (Nn / 8)           // 16384 8-row groups

// smem: per buffer q 256x144B (36864) + db 64x144B (9216) = 46080
#define F_QH   0
#define F_DH   36864
#define F_BUF  46080
#define SM_INVN 92160          // 64 floats
#define SM_TM   92448          // 256 q x 8 groups u32 = 8192
#define SMEM_TOTAL 100672      // x2 CTAs = 201344 -> 2 CTAs/SM

__device__ __nv_bfloat16 g_qh[Bq * Dk];
__device__ float g_invn[Nn];
__device__ unsigned g_tmax8[(size_t)Bq * NT8];  // per-(q, 8-row group) bf16-sim max

// ---------------- helpers ----------------
__device__ __forceinline__ uint32_t smem_u32(const void* p) {
    uint32_t a;
    asm("{ .reg .u64 t; cvta.to.shared.u64 t, %1; cvt.u32.u64 %0, t; }"
        : "=r"(a) : "l"(p));
    return a;
}
__device__ __forceinline__ unsigned sortable32(float v) {
    unsigned u = __float_as_uint(v);
    return (u & 0x80000000u) ? ~u : (u | 0x80000000u);
}
__device__ __forceinline__ float unsortable32(unsigned s) {
    unsigned u = (s & 0x80000000u) ? (s & 0x7fffffffu) : ~s;
    return __uint_as_float(u);
}
__device__ __forceinline__ unsigned long long pack_key(float v, unsigned idx) {
    return ((unsigned long long)sortable32(v) << 32) | (unsigned)(~idx);
}
__device__ __forceinline__ uint32_t b2u(__nv_bfloat162 h) {
    return *reinterpret_cast<uint32_t*>(&h);
}
__device__ __forceinline__ void cp_async16(uint32_t dst, const void* src) {
    asm volatile("cp.async.ca.shared.global [%0], [%1], 16;"
                 :: "r"(dst), "l"(src) : "memory");
}
__device__ __forceinline__ void cp_commit() {
    asm volatile("cp.async.commit_group;" ::: "memory");
}
__device__ __forceinline__ void cp_wait_all() {
    asm volatile("cp.async.wait_group 0;" ::: "memory");
}
__device__ __forceinline__ void ldsm_x4(uint32_t* r, uint32_t a) {
    asm volatile("ldmatrix.sync.aligned.m8n8.x4.shared.b16 {%0,%1,%2,%3}, [%4];"
                 : "=r"(r[0]), "=r"(r[1]), "=r"(r[2]), "=r"(r[3]) : "r"(a));
}
__device__ __forceinline__ void mma16816(float* d, const uint32_t* a, const uint32_t* b) {
    asm volatile(
        "mma.sync.aligned.m16n8k16.row.col.f32.bf16.bf16.f32 "
        "{%0,%1,%2,%3},{%4,%5,%6,%7},{%8,%9},{%0,%1,%2,%3};"
        : "+f"(d[0]), "+f"(d[1]), "+f"(d[2]), "+f"(d[3])
        : "r"(a[0]), "r"(a[1]), "r"(a[2]), "r"(a[3]), "r"(b[0]), "r"(b[1]));
}

// ---------------- convert queries ----------------
__global__ void convert_kernel(const float* __restrict__ x) {
    int i = blockIdx.x * 256 + threadIdx.x;
    g_qh[i] = __float2bfloat16(x[i]);
}

// ---------------- pass 1: 1-term bf16 GEMM, 256q x 64n per CTA, db read ONCE ----
// Raw-register db prefetch: LDG(c+1) issues before MMA(c), convert+store at c+1 top.
__global__ void __launch_bounds__(256, 2) sim_kernel(const float* __restrict__ db) {
    extern __shared__ char smem[];
    const uint32_t sb32 = smem_u32(smem);
    const int tid  = threadIdx.x;
    const int lane = tid & 31;
    const int w    = tid >> 5;
    const int n0   = blockIdx.x * 64;
    const int qb   = (w & 3) * 64;     // 64 queries per warp (4 x m16)
    const int nb   = (w >> 2) * 32;    // 32 db rows per warp (2 x n16)
    float* s_invn  = (float*)(smem + SM_INVN);
    unsigned* s_tm = (unsigned*)(smem + SM_TM);   // [256 q][8 groups]

    const int row = tid >> 2;          // db row 0..63
    const int kq  = tid & 3;           // 16-float slice within the 64-k chunk
    const float4* drow = (const float4*)(db + (size_t)(n0 + row) * Dk + kq * 16);

    float acc[4][4][4];
#pragma unroll
    for (int a = 0; a < 4; a++)
#pragma unroll
        for (int b = 0; b < 4; b++)
#pragma unroll
            for (int r = 0; r < 4; r++) acc[a][b][r] = 0.f;
    float ps = 0.f;

    // ---- prologue: q(0) cp.async, db(0) raw LDG ----
    float4 f0, f1, f2, f3;
    {
#pragma unroll
        for (int v = 0; v < 8; v++) {
            int ii  = tid + 256 * v;
            int qr  = ii >> 3;
            int c16 = ii & 7;
            cp_async16(sb32 + F_QH + qr * 144 + c16 * 16,
                       g_qh + (size_t)qr * Dk + c16 * 8);
        }
        cp_commit();
        f0 = drow[0]; f1 = drow[1]; f2 = drow[2]; f3 = drow[3];
    }

#pragma unroll 1
    for (int c = 0; c < 12; c++) {
        const int bufo = (c & 1) * F_BUF;
        // ---- 1. convert+store db chunk c from raw regs; fuse norms ----
        {
            ps = fmaf(f0.x, f0.x, fmaf(f0.y, f0.y, fmaf(f0.z, f0.z, fmaf(f0.w, f0.w, ps))));
            ps = fmaf(f1.x, f1.x, fmaf(f1.y, f1.y, fmaf(f1.z, f1.z, fmaf(f1.w, f1.w, ps))));
            ps = fmaf(f2.x, f2.x, fmaf(f2.y, f2.y, fmaf(f2.z, f2.z, fmaf(f2.w, f2.w, ps))));
            ps = fmaf(f3.x, f3.x, fmaf(f3.y, f3.y, fmaf(f3.z, f3.z, fmaf(f3.w, f3.w, ps))));
            char* ph = smem + bufo + F_DH + row * 144 + kq * 32;
            *(uint4*)(ph) = make_uint4(
                b2u(__floats2bfloat162_rn(f0.x, f0.y)), b2u(__floats2bfloat162_rn(f0.z, f0.w)),
                b2u(__floats2bfloat162_rn(f1.x, f1.y)), b2u(__floats2bfloat162_rn(f1.z, f1.w)));
            *(uint4*)(ph + 16) = make_uint4(
                b2u(__floats2bfloat162_rn(f2.x, f2.y)), b2u(__floats2bfloat162_rn(f2.z, f2.w)),
                b2u(__floats2bfloat162_rn(f3.x, f3.y)), b2u(__floats2bfloat162_rn(f3.z, f3.w)));
        }
        // ---- 2. q(c) arrived, tiles(c) complete across CTA ----
        cp_wait_all();
        __syncthreads();
        // ---- 3. issue q(c+1) cp.async + db(c+1) raw LDG (consumed next iter;
        //         DRAM latency hides under MMA(c)) ----
        if (c < 11) {
            const int bnxt = ((c + 1) & 1) * F_BUF;
            const int k1 = (c + 1) * 64;
#pragma unroll
            for (int v = 0; v < 8; v++) {
                int ii  = tid + 256 * v;
                int qr  = ii >> 3;
                int c16 = ii & 7;
                cp_async16(sb32 + bnxt + F_QH + qr * 144 + c16 * 16,
                           g_qh + (size_t)qr * Dk + k1 + c16 * 8);
            }
            cp_commit();
            const float4* dn = drow + (c + 1) * 16;   // 64 floats = 16 float4
            f0 = dn[0]; f1 = dn[1]; f2 = dn[2]; f3 = dn[3];
        }
        // ---- 4. MMA on chunk c ----
        const uint32_t sqh = sb32 + bufo + F_QH;
        const uint32_t sdh = sb32 + bufo + F_DH;
#pragma unroll
        for (int ks = 0; ks < 4; ks++) {
            uint32_t aH[4][4];
#pragma unroll
            for (int mi = 0; mi < 4; mi++) {
                uint32_t ao = (uint32_t)((qb + mi * 16 + (lane & 15)) * 144 +
                                         ks * 32 + (lane >> 4) * 16);
                ldsm_x4(aH[mi], sqh + ao);
            }
#pragma unroll
            for (int nip = 0; nip < 2; nip++) {
                uint32_t bo = (uint32_t)((nb + nip * 16 + (lane & 7) +
                                          ((lane >> 4) & 1) * 8) * 144 +
                                         ks * 32 + ((lane >> 3) & 1) * 16);
                uint32_t bh[4];
                ldsm_x4(bh, sdh + bo);
#pragma unroll
                for (int mi = 0; mi < 4; mi++)
#pragma unroll
                    for (int s = 0; s < 2; s++)
                        mma16816(acc[mi][nip * 2 + s], aH[mi], &bh[2 * s]);
            }
        }
        // no trailing sync: buffer reuse at c+2 ordered by the sync inside c+1
    }
    __syncthreads();   // all MMAs done before smem reuse

    // ---- inverse norms: 4 lanes (kq) share a row ----
    {
        float s = ps;
        s += __shfl_xor_sync(0xffffffffu, s, 1);
        s += __shfl_xor_sync(0xffffffffu, s, 2);
        if (kq == 0) {
            float r = 1.0f / fmaxf(sqrtf(s), 1e-8f);
            s_invn[row] = r;
            g_invn[n0 + row] = r;     // each db row owned by exactly one CTA
        }
    }
    __syncthreads();

    // ---- per-(q, 8-row group) max -> smem (R12-proven epilogue) ----
#pragma unroll
    for (int mi = 0; mi < 4; mi++)
#pragma unroll
        for (int j = 0; j < 4; j++) {
            int nl0 = nb + j * 8 + (lane & 3) * 2;
            float i0 = s_invn[nl0], i1 = s_invn[nl0 + 1];
            float m0 = fmaxf(acc[mi][j][0] * i0, acc[mi][j][1] * i1);
            float m1 = fmaxf(acc[mi][j][2] * i0, acc[mi][j][3] * i1);
            m0 = fmaxf(m0, __shfl_xor_sync(0xffffffffu, m0, 1));
            m0 = fmaxf(m0, __shfl_xor_sync(0xffffffffu, m0, 2));
            m1 = fmaxf(m1, __shfl_xor_sync(0xffffffffu, m1, 1));
            m1 = fmaxf(m1, __shfl_xor_sync(0xffffffffu, m1, 2));
            if ((lane & 3) == 0) {
                int g = (nb >> 3) + j;
                s_tm[(qb + mi * 16 + (lane >> 2)) * 8 + g]     = sortable32(m0);
                s_tm[(qb + mi * 16 + (lane >> 2) + 8) * 8 + g] = sortable32(m1);
            }
        }
    __syncthreads();
    {
        uint4* dst = (uint4*)(g_tmax8 + (size_t)tid * NT8 + (n0 >> 3));
        const unsigned* src = s_tm + tid * 8;
        dst[0] = make_uint4(src[0], src[1], src[2], src[3]);
        dst[1] = make_uint4(src[4], src[5], src[6], src[7]);
    }
}

// ---------------- pass 2 (fused): filter + exact rescore + gather, 1 block/query ----
__global__ void __launch_bounds__(256) finalize_kernel(const float* __restrict__ x,
                                                       const float* __restrict__ db,
                                                       const float* __restrict__ y,
                                                       float* __restrict__ out) {
    const int q = blockIdx.x;
    const int tid  = threadIdx.x;
    const int lane = tid & 31;
    const int warp = tid >> 5;
    __shared__ unsigned s_red[256];
    __shared__ unsigned s_cand[256];
    __shared__ int s_cnt;
    __shared__ unsigned long long s_best;
    __shared__ float xq[Dk];

    if (tid == 0) { s_cnt = 0; s_best = 0ull; }
    const unsigned* tm = g_tmax8 + (size_t)q * NT8;
    unsigned v[64];
    unsigned m = 0;
#pragma unroll
    for (int i = 0; i < 64; i++) {
        v[i] = tm[tid + 256 * i];      // coalesced
        m = m > v[i] ? m : v[i];
    }
    s_red[tid] = m;
    __syncthreads();
#pragma unroll
    for (int s = 128; s; s >>= 1) {
        if (tid < s) {
            unsigned o = s_red[tid + s];
            if (o > s_red[tid]) s_red[tid] = o;
        }
        __syncthreads();
    }
    const unsigned thr = sortable32(unsortable32(s_red[0]) - MARGIN);
#pragma unroll
    for (int i = 0; i < 64; i++) {
        if (v[i] >= thr) {
            int slot = atomicAdd(&s_cnt, 1);
            if (slot < 256) s_cand[slot] = (unsigned)(tid + 256 * i);
        }
    }
    // stage query into smem while candidates settle
    for (int j = tid; j < Dk; j += 256) xq[j] = x[(size_t)q * Dk + j];
    __syncthreads();

    int ncand = s_cnt < 256 ? s_cnt : 256;
    unsigned long long best = 0ull;
    for (int r = warp; r < ncand * 8; r += 8) {
        int n = (int)s_cand[r >> 3] * 8 + (r & 7);
        const float* d = db + (size_t)n * Dk;
        float s = 0.f;
#pragma unroll
        for (int j = 0; j < 24; j++)
            s = fmaf(xq[j * 32 + lane], d[j * 32 + lane], s);
#pragma unroll
        for (int mm = 16; mm; mm >>= 1) s += __shfl_xor_sync(0xffffffffu, s, mm);
        if (lane == 0) {
            unsigned long long cand = pack_key(s * g_invn[n], (unsigned)n);
            best = (cand > best) ? cand : best;
        }
    }
    if (lane == 0 && best) atomicMax(&s_best, best);
    __syncthreads();

    // gather the winning y row
    const unsigned idx = ~((unsigned)(s_best & 0xffffffffull));
    const float* src = y + (size_t)idx * Lo;
    float* dst = out + (size_t)q * Lo;
    dst[tid]       = src[tid];
    dst[tid + 256] = src[tid + 256];
}

extern "C" void kernel_launch(void* const* d_in, const int* in_sizes, int n_in,
                              void* d_out, int out_size) {
    const float* imu = (const float*)d_in[0];
    const float* dbx = (const float*)d_in[1];
    const float* dby = (const float*)d_in[2];
    float* out = (float*)d_out;

    cudaFuncSetAttribute(sim_kernel, cudaFuncAttributeMaxDynamicSharedMemorySize,
                         SMEM_TOTAL);

    convert_kernel<<<Dk, 256>>>(imu);
    sim_kernel<<<Nn / 64, 256, SMEM_TOTAL>>>(dbx);
    finalize_kernel<<<Bq, 256>>>(imu, dbx, dby, out);
}

// round 15
// speedup vs baseline: 1.2735x; 1.2735x over previous
#include <cuda_runtime.h>
#include <cuda_bf16.h>
#include <cstdint>

#define Bq 256      // queries
#define Dk 768      // feature dim
#define Nn 131072   // database rows
#define Lo 512      // output row length

#define MARGIN 0.6f
#define CAND_CAP 16384
#define NT8 (Nn / 8)           // 16384 8-row groups

// smem: per buffer q 256x80B (20480) + db 64x80B (5120) = 25600
#define F_QH   0
#define F_DH   20480
#define F_BUF  25600
#define SM_INVN 51200          // 64 floats (256 B)
#define SM_TM   51456          // 256 q x 8 groups u32 = 8192
#define SMEM_TOTAL 59680       // x2 CTAs = 119360 -> 2 CTAs/SM

__device__ unsigned char g_q8[Bq * Dk];         // queries in e4m3
__device__ float g_invn[Nn];
__device__ unsigned g_tmax8[(size_t)Bq * NT8];  // per-(q, 8-row group) fp8-sim max
__device__ unsigned long long g_best2[Bq];      // exact argmax keys
__device__ int g_cand_count;
__device__ unsigned g_cand[CAND_CAP];           // (q << 14) | tile8

// ---------------- helpers ----------------
__device__ __forceinline__ uint32_t smem_u32(const void* p) {
    uint32_t a;
    asm("{ .reg .u64 t; cvta.to.shared.u64 t, %1; cvt.u32.u64 %0, t; }"
        : "=r"(a) : "l"(p));
    return a;
}
__device__ __forceinline__ unsigned sortable32(float v) {
    unsigned u = __float_as_uint(v);
    return (u & 0x80000000u) ? ~u : (u | 0x80000000u);
}
__device__ __forceinline__ float unsortable32(unsigned s) {
    unsigned u = (s & 0x80000000u) ? (s & 0x7fffffffu) : ~s;
    return __uint_as_float(u);
}
__device__ __forceinline__ unsigned long long pack_key(float v, unsigned idx) {
    return ((unsigned long long)sortable32(v) << 32) | (unsigned)(~idx);
}
// pack 4 fp32 -> 4 e4m3 bytes (x lowest byte)
__device__ __forceinline__ uint32_t f4_e4m3(float4 f) {
    unsigned short lo, hi;
    asm("cvt.rn.satfinite.e4m3x2.f32 %0, %1, %2;" : "=h"(lo) : "f"(f.y), "f"(f.x));
    asm("cvt.rn.satfinite.e4m3x2.f32 %0, %1, %2;" : "=h"(hi) : "f"(f.w), "f"(f.z));
    return (uint32_t)lo | ((uint32_t)hi << 16);
}
__device__ __forceinline__ void cp_async16(uint32_t dst, const void* src) {
    asm volatile("cp.async.ca.shared.global [%0], [%1], 16;"
                 :: "r"(dst), "l"(src) : "memory");
}
__device__ __forceinline__ void cp_commit() {
    asm volatile("cp.async.commit_group;" ::: "memory");
}
__device__ __forceinline__ void cp_wait_all() {
    asm volatile("cp.async.wait_group 0;" ::: "memory");
}
__device__ __forceinline__ void ldsm_x4(uint32_t* r, uint32_t a) {
    asm volatile("ldmatrix.sync.aligned.m8n8.x4.shared.b16 {%0,%1,%2,%3}, [%4];"
                 : "=r"(r[0]), "=r"(r[1]), "=r"(r[2]), "=r"(r[3]) : "r"(a));
}
// fp8 e4m3 MMA: m16n8k32, fragments byte-identical to bf16 m16n8k16
__device__ __forceinline__ void mma_fp8(float* d, const uint32_t* a, const uint32_t* b) {
    asm volatile(
        "mma.sync.aligned.m16n8k32.row.col.f32.e4m3.e4m3.f32 "
        "{%0,%1,%2,%3},{%4,%5,%6,%7},{%8,%9},{%0,%1,%2,%3};"
        : "+f"(d[0]), "+f"(d[1]), "+f"(d[2]), "+f"(d[3])
        : "r"(a[0]), "r"(a[1]), "r"(a[2]), "r"(a[3]), "r"(b[0]), "r"(b[1]));
}

// ---------------- convert queries to e4m3 + init ----------------
__global__ void convert_init_kernel(const float* __restrict__ x) {
    int i = blockIdx.x * 256 + threadIdx.x;          // 192 blocks x 256 = 49152
    float4 f = ((const float4*)x)[i];
    ((uint32_t*)g_q8)[i] = f4_e4m3(f);
    if (blockIdx.x == 0) {
        g_best2[threadIdx.x] = 0ull;
        if (threadIdx.x == 0) g_cand_count = 0;
    }
}

// ---------------- pass 1: fp8 GEMM, 256q x 64n per CTA, db read ONCE ----------
__global__ void __launch_bounds__(256, 2) sim_kernel(const float* __restrict__ db) {
    extern __shared__ char smem[];
    const uint32_t sb32 = smem_u32(smem);
    const int tid  = threadIdx.x;
    const int lane = tid & 31;
    const int w    = tid >> 5;
    const int n0   = blockIdx.x * 64;
    const int qb   = (w & 3) * 64;     // 64 queries per warp (4 x m16)
    const int nb   = (w >> 2) * 32;    // 32 db rows per warp (2 x n16)
    float* s_invn  = (float*)(smem + SM_INVN);
    unsigned* s_tm = (unsigned*)(smem + SM_TM);   // [256 q][8 groups]

    const int row = tid >> 2;          // db row 0..63
    const int kq  = tid & 3;           // 16-float slice within the 64-k chunk

    float acc[4][4][4];
#pragma unroll
    for (int a = 0; a < 4; a++)
#pragma unroll
        for (int b = 0; b < 4; b++)
#pragma unroll
            for (int r = 0; r < 4; r++) acc[a][b][r] = 0.f;
    float ps = 0.f;

#pragma unroll 1
    for (int c = 0; c < 12; c++) {
        const int bufo = (c & 1) * F_BUF;
        const int k0 = c * 64;
        // ---- q tile (256 rows x 64 fp8 = 64B/row) via cp.async: 4 x 16B/thread ----
        {
#pragma unroll
            for (int v = 0; v < 4; v++) {
                int ii  = tid + 256 * v;      // 0..1023
                int qr  = ii >> 2;            // 0..255
                int c16 = ii & 3;             // 4 x 16B per row
                cp_async16(sb32 + bufo + F_QH + qr * 80 + c16 * 16,
                           g_q8 + (size_t)qr * Dk + k0 + c16 * 16);
            }
            cp_commit();
        }
        // ---- db tile (64 rows x 64k): fp32 -> e4m3, fuse norms; 4 LDG.128/thread ----
        {
            const float4* dsrc = (const float4*)(db + (size_t)(n0 + row) * Dk + k0 + kq * 16);
            float4 f0 = dsrc[0], f1 = dsrc[1], f2 = dsrc[2], f3 = dsrc[3];
            ps = fmaf(f0.x, f0.x, fmaf(f0.y, f0.y, fmaf(f0.z, f0.z, fmaf(f0.w, f0.w, ps))));
            ps = fmaf(f1.x, f1.x, fmaf(f1.y, f1.y, fmaf(f1.z, f1.z, fmaf(f1.w, f1.w, ps))));
            ps = fmaf(f2.x, f2.x, fmaf(f2.y, f2.y, fmaf(f2.z, f2.z, fmaf(f2.w, f2.w, ps))));
            ps = fmaf(f3.x, f3.x, fmaf(f3.y, f3.y, fmaf(f3.z, f3.z, fmaf(f3.w, f3.w, ps))));
            *(uint4*)(smem + bufo + F_DH + row * 80 + kq * 16) =
                make_uint4(f4_e4m3(f0), f4_e4m3(f1), f4_e4m3(f2), f4_e4m3(f3));
        }
        cp_wait_all();
        __syncthreads();   // single sync per chunk

        const uint32_t sqh = sb32 + bufo + F_QH;
        const uint32_t sdh = sb32 + bufo + F_DH;
#pragma unroll
        for (int ks = 0; ks < 2; ks++) {       // 2 x k32 covers the 64-k chunk
            uint32_t aH[4][4];
#pragma unroll
            for (int mi = 0; mi < 4; mi++) {
                uint32_t ao = (uint32_t)((qb + mi * 16 + (lane & 15)) * 80 +
                                         ks * 32 + (lane >> 4) * 16);
                ldsm_x4(aH[mi], sqh + ao);
            }
#pragma unroll
            for (int nip = 0; nip < 2; nip++) {
                uint32_t bo = (uint32_t)((nb + nip * 16 + (lane & 7) +
                                          ((lane >> 4) & 1) * 8) * 80 +
                                         ks * 32 + ((lane >> 3) & 1) * 16);
                uint32_t bh[4];
                ldsm_x4(bh, sdh + bo);
#pragma unroll
                for (int mi = 0; mi < 4; mi++)
#pragma unroll
                    for (int s = 0; s < 2; s++)
                        mma_fp8(acc[mi][nip * 2 + s], aH[mi], &bh[2 * s]);
            }
        }
        // no trailing sync: buffer reuse at c+2 ordered by the sync inside c+1
    }
    __syncthreads();   // all MMAs done before smem reuse

    // ---- inverse norms: 4 lanes (kq) share a row ----
    {
        float s = ps;
        s += __shfl_xor_sync(0xffffffffu, s, 1);
        s += __shfl_xor_sync(0xffffffffu, s, 2);
        if (kq == 0) {
            float r = 1.0f / fmaxf(sqrtf(s), 1e-8f);
            s_invn[row] = r;
            g_invn[n0 + row] = r;     // each db row owned by exactly one CTA
        }
    }
    __syncthreads();

    // ---- per-(q, 8-row group) max -> smem (R12-proven epilogue) ----
#pragma unroll
    for (int mi = 0; mi < 4; mi++)
#pragma unroll
        for (int j = 0; j < 4; j++) {
            int nl0 = nb + j * 8 + (lane & 3) * 2;
            float i0 = s_invn[nl0], i1 = s_invn[nl0 + 1];
            float m0 = fmaxf(acc[mi][j][0] * i0, acc[mi][j][1] * i1);
            float m1 = fmaxf(acc[mi][j][2] * i0, acc[mi][j][3] * i1);
            m0 = fmaxf(m0, __shfl_xor_sync(0xffffffffu, m0, 1));
            m0 = fmaxf(m0, __shfl_xor_sync(0xffffffffu, m0, 2));
            m1 = fmaxf(m1, __shfl_xor_sync(0xffffffffu, m1, 1));
            m1 = fmaxf(m1, __shfl_xor_sync(0xffffffffu, m1, 2));
            if ((lane & 3) == 0) {
                int g = (nb >> 3) + j;
                s_tm[(qb + mi * 16 + (lane >> 2)) * 8 + g]     = sortable32(m0);
                s_tm[(qb + mi * 16 + (lane >> 2) + 8) * 8 + g] = sortable32(m1);
            }
        }
    __syncthreads();
    {
        uint4* dst = (uint4*)(g_tmax8 + (size_t)tid * NT8 + (n0 >> 3));
        const unsigned* src = s_tm + tid * 8;
        dst[0] = make_uint4(src[0], src[1], src[2], src[3]);
        dst[1] = make_uint4(src[4], src[5], src[6], src[7]);
    }
}

// ---------------- pass 2: per-query tile8 filter ----------------
__global__ void __launch_bounds__(256) reduce_kernel() {
    const int q = blockIdx.x;
    const int tid = threadIdx.x;
    __shared__ unsigned s_red[256];
    const unsigned* tm = g_tmax8 + (size_t)q * NT8;

    unsigned m = 0;
    unsigned v[64];
#pragma unroll
    for (int i = 0; i < 64; i++) {
        v[i] = tm[tid + 256 * i];
        m = m > v[i] ? m : v[i];
    }
    s_red[tid] = m;
    __syncthreads();
#pragma unroll
    for (int s = 128; s; s >>= 1) {
        if (tid < s) {
            unsigned o = s_red[tid + s];
            if (o > s_red[tid]) s_red[tid] = o;
        }
        __syncthreads();
    }
    const unsigned thr = sortable32(unsortable32(s_red[0]) - MARGIN);
#pragma unroll
    for (int i = 0; i < 64; i++) {
        if (v[i] >= thr) {
            int slot = atomicAdd(&g_cand_count, 1);
            if (slot < CAND_CAP)
                g_cand[slot] = ((unsigned)q << 14) | (unsigned)(tid + 256 * i);
        }
    }
}

// ---------------- pass 3: exact fp32 rescore (one warp per row, 8 rows/cand) ----
__global__ void __launch_bounds__(256) rescore_kernel(const float* __restrict__ x,
                                                      const float* __restrict__ db) {
    __shared__ float xq[Dk];
    const int tid  = threadIdx.x;
    const int lane = tid & 31;
    const int warp = tid >> 5;
    int cnt = g_cand_count;
    if (cnt > CAND_CAP) cnt = CAND_CAP;

    for (int i = blockIdx.x; i < cnt; i += gridDim.x) {
        unsigned c = g_cand[i];
        unsigned q = c >> 14;
        unsigned t = c & 16383u;
        for (int j = tid; j < Dk; j += 256) xq[j] = x[(size_t)q * Dk + j];
        __syncthreads();
        int n = (int)t * 8 + warp;
        const float* d = db + (size_t)n * Dk;
        float s = 0.f;
#pragma unroll
        for (int j = 0; j < 24; j++)
            s = fmaf(xq[j * 32 + lane], d[j * 32 + lane], s);
#pragma unroll
        for (int mm = 16; mm; mm >>= 1) s += __shfl_xor_sync(0xffffffffu, s, mm);
        if (lane == 0)
            atomicMax(&g_best2[q], pack_key(s * g_invn[n], (unsigned)n));
        __syncthreads();
    }
}

// ---------------- gather ----------------
__global__ void gather_kernel(const float* __restrict__ y, float* __restrict__ out) {
    const int b = blockIdx.x;
    unsigned idx = ~((unsigned)(g_best2[b] & 0xffffffffull));
    const float4* src = (const float4*)(y + (size_t)idx * Lo);
    float4* dst = (float4*)(out + (size_t)b * Lo);
    dst[threadIdx.x] = src[threadIdx.x];
}

extern "C" void kernel_launch(void* const* d_in, const int* in_sizes, int n_in,
                              void* d_out, int out_size) {
    const float* imu = (const float*)d_in[0];
    const float* dbx = (const float*)d_in[1];
    const float* dby = (const float*)d_in[2];
    float* out = (float*)d_out;

    cudaFuncSetAttribute(sim_kernel, cudaFuncAttributeMaxDynamicSharedMemorySize,
                         SMEM_TOTAL);

    convert_init_kernel<<<Bq * Dk / 4 / 256, 256>>>(imu);
    sim_kernel<<<Nn / 64, 256, SMEM_TOTAL>>>(dbx);
    reduce_kernel<<<Bq, 256>>>();
    rescore_kernel<<<512, 256>>>(imu, dbx);
    gather_kernel<<<Bq, Lo / 4>>>(dby, out);
}